// round 1
// baseline (speedup 1.0000x reference)
#include <cuda_runtime.h>

// SortingRegressionModel: out[i] = sort(x[i,0..2]) . W + b
// Pure streaming kernel: 96 MB read + 32 MB write => HBM-bound, ~20us floor.
//
// Each thread handles 4 rows = 12 floats = 3 aligned float4 loads,
// writes 4 outputs as one float4 store.

__global__ void __launch_bounds__(256) sort3_linear_kernel(
    const float4* __restrict__ x4,   // x viewed as float4[], 3 per thread-chunk
    const float*  __restrict__ Wp,   // 3 weights
    const float*  __restrict__ bp,   // 1 bias
    float4*       __restrict__ out4, // output viewed as float4[]
    int n_chunks)                    // number of 4-row chunks (= B/4)
{
    int t = blockIdx.x * blockDim.x + threadIdx.x;
    if (t >= n_chunks) return;

    // Uniform loads -> L1 broadcast, negligible cost.
    const float w0 = __ldg(Wp + 0);
    const float w1 = __ldg(Wp + 1);
    const float w2 = __ldg(Wp + 2);
    const float bias = __ldg(bp);

    // 3 independent 128-bit loads (MLP=3, front-batched).
    const float4 p = x4[3 * t + 0];  // rows: r0(a,b,c) r1(a)
    const float4 q = x4[3 * t + 1];  // rows: r1(b,c) r2(a,b)
    const float4 r = x4[3 * t + 2];  // rows: r2(c) r3(a,b,c)

    float4 o;
    {
        // row 0: p.x p.y p.z
        float mn = fminf(p.x, p.y), mx = fmaxf(p.x, p.y);
        float lo = fminf(mn, p.z);
        float hi = fmaxf(mx, p.z);
        float mid = fmaxf(mn, fminf(mx, p.z));
        o.x = fmaf(lo, w0, fmaf(mid, w1, fmaf(hi, w2, bias)));
    }
    {
        // row 1: p.w q.x q.y
        float mn = fminf(p.w, q.x), mx = fmaxf(p.w, q.x);
        float lo = fminf(mn, q.y);
        float hi = fmaxf(mx, q.y);
        float mid = fmaxf(mn, fminf(mx, q.y));
        o.y = fmaf(lo, w0, fmaf(mid, w1, fmaf(hi, w2, bias)));
    }
    {
        // row 2: q.z q.w r.x
        float mn = fminf(q.z, q.w), mx = fmaxf(q.z, q.w);
        float lo = fminf(mn, r.x);
        float hi = fmaxf(mx, r.x);
        float mid = fmaxf(mn, fminf(mx, r.x));
        o.z = fmaf(lo, w0, fmaf(mid, w1, fmaf(hi, w2, bias)));
    }
    {
        // row 3: r.y r.z r.w
        float mn = fminf(r.y, r.z), mx = fmaxf(r.y, r.z);
        float lo = fminf(mn, r.w);
        float hi = fmaxf(mx, r.w);
        float mid = fmaxf(mn, fminf(mx, r.w));
        o.w = fmaf(lo, w0, fmaf(mid, w1, fmaf(hi, w2, bias)));
    }

    out4[t] = o;
}

// Tail kernel for rows not covered by the vectorized path (B % 4 != 0).
__global__ void sort3_linear_tail_kernel(
    const float* __restrict__ x,
    const float* __restrict__ Wp,
    const float* __restrict__ bp,
    float*       __restrict__ out,
    int start_row, int n_rows)
{
    int i = start_row + blockIdx.x * blockDim.x + threadIdx.x;
    if (i >= n_rows) return;
    float a = x[3 * i + 0], b = x[3 * i + 1], c = x[3 * i + 2];
    float mn = fminf(a, b), mx = fmaxf(a, b);
    float lo = fminf(mn, c);
    float hi = fmaxf(mx, c);
    float mid = fmaxf(mn, fminf(mx, c));
    out[i] = fmaf(lo, __ldg(Wp + 0),
             fmaf(mid, __ldg(Wp + 1),
             fmaf(hi, __ldg(Wp + 2), __ldg(bp))));
}

extern "C" void kernel_launch(void* const* d_in, const int* in_sizes, int n_in,
                              void* d_out, int out_size)
{
    const float* x = (const float*)d_in[0];   // [B, 3]
    const float* W = (const float*)d_in[1];   // [1, 3]
    const float* b = (const float*)d_in[2];   // [1]
    float* out = (float*)d_out;               // [B, 1]

    const int B = in_sizes[0] / 3;
    const int n_chunks = B / 4;          // 4 rows per thread (vectorized path)
    const int tail_start = n_chunks * 4;

    if (n_chunks > 0) {
        const int threads = 256;
        const int blocks = (n_chunks + threads - 1) / threads;
        sort3_linear_kernel<<<blocks, threads>>>(
            (const float4*)x, W, b, (float4*)out, n_chunks);
    }
    if (tail_start < B) {
        const int n_tail = B - tail_start;
        sort3_linear_tail_kernel<<<(n_tail + 255) / 256, 256>>>(
            x, W, b, out, tail_start, B);
    }
}